// round 13
// baseline (speedup 1.0000x reference)
#include <cuda_runtime.h>
#include <cstdint>

// scatter_mean via counting-sort + gather (v4 — atomic-free placement):
//   k0: zero counters
//   k1: fused histogram: lpos = atomicAdd(cnt[s],1) stored coalesced to g_lpos
//   k2a/b/c: 3-phase multi-block exclusive scan -> g_off
//   k3: place: g_rowid[g_off[s] + lpos] = row   (no atomics, scattered STG)
//   k4: gather-reduce (R8 version): 1 warp/segment, float2, 8 rows in flight
//
// x: [N, 64] f32, index: [N] int32, out: [S, 64] f32  (N=4194304, S=100000)

#define S_MAX 100000
#define N_MAX 4194304
#define SCAN_BLK 1024
#define NB_MAX 128

__device__ int g_cnt[S_MAX];
__device__ int g_off[S_MAX];
__device__ int g_bsum[NB_MAX];
__device__ int g_lpos[N_MAX];
__device__ int g_rowid[N_MAX];

__global__ void zero_kernel(int S) {
    int i = blockIdx.x * blockDim.x + threadIdx.x;
    if (i < S) g_cnt[i] = 0;
}

// Fused histogram: atomic returns local position within segment.
__global__ void hist_kernel(const int4* __restrict__ idx4, int nquads) {
    int i = (blockIdx.x * blockDim.x + threadIdx.x) * 2;
    if (i >= nquads) return;
    int4 a = idx4[i];
    int4 b = (i + 1 < nquads) ? idx4[i + 1] : make_int4(0, 0, 0, 0);

    int p0 = atomicAdd(&g_cnt[a.x], 1);
    int p1 = atomicAdd(&g_cnt[a.y], 1);
    int p2 = atomicAdd(&g_cnt[a.z], 1);
    int p3 = atomicAdd(&g_cnt[a.w], 1);
    int4 la; la.x = p0; la.y = p1; la.z = p2; la.w = p3;
    ((int4*)g_lpos)[i] = la;                       // coalesced

    if (i + 1 < nquads) {
        int p4 = atomicAdd(&g_cnt[b.x], 1);
        int p5 = atomicAdd(&g_cnt[b.y], 1);
        int p6 = atomicAdd(&g_cnt[b.z], 1);
        int p7 = atomicAdd(&g_cnt[b.w], 1);
        int4 lb; lb.x = p4; lb.y = p5; lb.z = p6; lb.w = p7;
        ((int4*)g_lpos)[i + 1] = lb;
    }
}

__global__ void scanA_kernel(int S) {
    __shared__ int warp_sums[32];
    int tid = threadIdx.x;
    int lane = tid & 31;
    int wid = tid >> 5;
    int i = blockIdx.x * SCAN_BLK + tid;
    int c = (i < S) ? g_cnt[i] : 0;

    int v = c;
    #pragma unroll
    for (int d = 1; d < 32; d <<= 1) {
        int n = __shfl_up_sync(0xFFFFFFFFu, v, d);
        if (lane >= d) v += n;
    }
    if (lane == 31) warp_sums[wid] = v;
    __syncthreads();
    if (wid == 0) {
        int w = warp_sums[lane];
        #pragma unroll
        for (int d = 1; d < 32; d <<= 1) {
            int n = __shfl_up_sync(0xFFFFFFFFu, w, d);
            if (lane >= d) w += n;
        }
        warp_sums[lane] = w;
    }
    __syncthreads();

    int warp_off = (wid == 0) ? 0 : warp_sums[wid - 1];
    if (i < S) g_off[i] = warp_off + v - c;
    if (tid == 0) g_bsum[blockIdx.x] = warp_sums[31];
}

__global__ void scanB_kernel(int NB) {
    __shared__ int sm[NB_MAX];
    int tid = threadIdx.x;
    int c = (tid < NB) ? g_bsum[tid] : 0;
    sm[tid] = c;
    __syncthreads();
    #pragma unroll
    for (int d = 1; d < NB_MAX; d <<= 1) {
        int t = (tid >= d) ? sm[tid - d] : 0;
        __syncthreads();
        sm[tid] += t;
        __syncthreads();
    }
    if (tid < NB) g_bsum[tid] = sm[tid] - c;
}

__global__ void scanC_kernel(int S) {
    int i = blockIdx.x * SCAN_BLK + threadIdx.x;
    if (i >= S) return;
    g_off[i] += g_bsum[blockIdx.x];
}

// Atomic-free placement: two coalesced reads + one scattered 4B store per row.
__global__ void place_kernel(const int4* __restrict__ idx4, int nquads) {
    int i = (blockIdx.x * blockDim.x + threadIdx.x) * 2;
    if (i >= nquads) return;
    int4 a = idx4[i];
    int4 la = ((const int4*)g_lpos)[i];
    int r = i * 4;
    g_rowid[g_off[a.x] + la.x] = r + 0;
    g_rowid[g_off[a.y] + la.y] = r + 1;
    g_rowid[g_off[a.z] + la.z] = r + 2;
    g_rowid[g_off[a.w] + la.w] = r + 3;
    if (i + 1 < nquads) {
        int4 b = idx4[i + 1];
        int4 lb = ((const int4*)g_lpos)[i + 1];
        g_rowid[g_off[b.x] + lb.x] = r + 4;
        g_rowid[g_off[b.y] + lb.y] = r + 5;
        g_rowid[g_off[b.z] + lb.z] = r + 6;
        g_rowid[g_off[b.w] + lb.w] = r + 7;
    }
}

// R8's reduce: one warp per segment, float2, 8 rows in flight, fused divide.
__global__ void reduce_kernel(const float2* __restrict__ x2,
                              float2* __restrict__ out2,
                              int S) {
    int gw = (blockIdx.x * blockDim.x + threadIdx.x) >> 5;
    int lane = threadIdx.x & 31;
    if (gw >= S) return;

    int start = g_off[gw];
    int cnt   = g_cnt[gw];

    float2 acc0 = {0.f, 0.f}, acc1 = {0.f, 0.f};
    int i = 0;
    for (; i + 8 <= cnt; i += 8) {
        int r0 = g_rowid[start + i + 0];
        int r1 = g_rowid[start + i + 1];
        int r2 = g_rowid[start + i + 2];
        int r3 = g_rowid[start + i + 3];
        int r4 = g_rowid[start + i + 4];
        int r5 = g_rowid[start + i + 5];
        int r6 = g_rowid[start + i + 6];
        int r7 = g_rowid[start + i + 7];
        float2 v0 = __ldcs(x2 + (long long)r0 * 32 + lane);
        float2 v1 = __ldcs(x2 + (long long)r1 * 32 + lane);
        float2 v2 = __ldcs(x2 + (long long)r2 * 32 + lane);
        float2 v3 = __ldcs(x2 + (long long)r3 * 32 + lane);
        float2 v4 = __ldcs(x2 + (long long)r4 * 32 + lane);
        float2 v5 = __ldcs(x2 + (long long)r5 * 32 + lane);
        float2 v6 = __ldcs(x2 + (long long)r6 * 32 + lane);
        float2 v7 = __ldcs(x2 + (long long)r7 * 32 + lane);
        acc0.x += v0.x + v2.x + v4.x + v6.x;
        acc0.y += v0.y + v2.y + v4.y + v6.y;
        acc1.x += v1.x + v3.x + v5.x + v7.x;
        acc1.y += v1.y + v3.y + v5.y + v7.y;
    }
    for (; i < cnt; i++) {
        int r = g_rowid[start + i];
        float2 v = __ldcs(x2 + (long long)r * 32 + lane);
        acc0.x += v.x; acc0.y += v.y;
    }

    float inv = 1.0f / (float)max(cnt, 1);
    float2 o;
    o.x = (acc0.x + acc1.x) * inv;
    o.y = (acc0.y + acc1.y) * inv;
    out2[(long long)gw * 32 + lane] = o;
}

extern "C" void kernel_launch(void* const* d_in, const int* in_sizes, int n_in,
                              void* d_out, int out_size) {
    const float2* x2   = (const float2*)d_in[0];
    const int4*   idx4 = (const int4*)d_in[1];
    float2*       out2 = (float2*)d_out;

    int nrows  = in_sizes[1];        // 4194304
    int S      = out_size / 64;      // 100000
    int nquads = nrows / 4;          // 1048576
    int NB     = (S + SCAN_BLK - 1) / SCAN_BLK;   // 98

    {
        int threads = 256;
        zero_kernel<<<(S + threads - 1) / threads, threads>>>(S);
    }
    {
        int threads = 256;
        int nth = (nquads + 1) / 2;
        hist_kernel<<<(nth + threads - 1) / threads, threads>>>(idx4, nquads);
    }
    scanA_kernel<<<NB, SCAN_BLK>>>(S);
    scanB_kernel<<<1, NB_MAX>>>(NB);
    scanC_kernel<<<NB, SCAN_BLK>>>(S);
    {
        int threads = 256;
        int nth = (nquads + 1) / 2;
        place_kernel<<<(nth + threads - 1) / threads, threads>>>(idx4, nquads);
    }
    {
        int threads = 256;
        int blocks = (S * 32 + threads - 1) / threads;
        reduce_kernel<<<blocks, threads>>>(x2, out2, S);
    }
}

// round 15
// speedup vs baseline: 1.0911x; 1.0911x over previous
#include <cuda_runtime.h>
#include <cstdint>

// scatter_mean via counting-sort + gather (v5 = R8 + prep cuts):
//   k0: zero counters
//   k1: histogram (REDG fire-and-forget, result unused)
//   k2a: per-block exclusive scan -> g_cur (block-local), block sums -> g_bsum
//   k2b: exclusive scan of block sums (single block)
//   k3: bucket: pos = atomicAdd(g_cur[s]) + g_bsum[s>>10]  (scanC fused away)
//   k4: gather-reduce (R8): start = g_cur_base... = local_off + bsum
//
// x: [N, 64] f32, index: [N] int32, out: [S, 64] f32  (N=4194304, S=100000)

#define S_MAX 100000
#define N_MAX 4194304
#define SCAN_BLK 1024
#define NB_MAX 128

__device__ int g_cnt[S_MAX];
__device__ int g_loc[S_MAX];     // block-local exclusive offsets (immutable)
__device__ int g_cur[S_MAX];     // cursor, seeded with block-local offsets
__device__ int g_bsum[NB_MAX];
__device__ int g_rowid[N_MAX];

__global__ void zero_kernel(int S) {
    int i = blockIdx.x * blockDim.x + threadIdx.x;
    if (i < S) g_cnt[i] = 0;
}

__global__ void hist_kernel(const int4* __restrict__ idx4, int nquads) {
    int i = (blockIdx.x * blockDim.x + threadIdx.x) * 2;
    if (i >= nquads) return;
    int4 a = idx4[i];
    atomicAdd(&g_cnt[a.x], 1);          // result unused -> REDG
    atomicAdd(&g_cnt[a.y], 1);
    atomicAdd(&g_cnt[a.z], 1);
    atomicAdd(&g_cnt[a.w], 1);
    if (i + 1 < nquads) {
        int4 b = idx4[i + 1];
        atomicAdd(&g_cnt[b.x], 1);
        atomicAdd(&g_cnt[b.y], 1);
        atomicAdd(&g_cnt[b.z], 1);
        atomicAdd(&g_cnt[b.w], 1);
    }
}

// Per-block exclusive scan; writes block-local offsets to BOTH g_loc and g_cur.
__global__ void scanA_kernel(int S) {
    __shared__ int warp_sums[32];
    int tid = threadIdx.x;
    int lane = tid & 31;
    int wid = tid >> 5;
    int i = blockIdx.x * SCAN_BLK + tid;
    int c = (i < S) ? g_cnt[i] : 0;

    int v = c;
    #pragma unroll
    for (int d = 1; d < 32; d <<= 1) {
        int n = __shfl_up_sync(0xFFFFFFFFu, v, d);
        if (lane >= d) v += n;
    }
    if (lane == 31) warp_sums[wid] = v;
    __syncthreads();
    if (wid == 0) {
        int w = warp_sums[lane];
        #pragma unroll
        for (int d = 1; d < 32; d <<= 1) {
            int n = __shfl_up_sync(0xFFFFFFFFu, w, d);
            if (lane >= d) w += n;
        }
        warp_sums[lane] = w;
    }
    __syncthreads();

    int warp_off = (wid == 0) ? 0 : warp_sums[wid - 1];
    if (i < S) {
        int excl = warp_off + v - c;
        g_loc[i] = excl;
        g_cur[i] = excl;
    }
    if (tid == 0) g_bsum[blockIdx.x] = warp_sums[31];
}

__global__ void scanB_kernel(int NB) {
    __shared__ int sm[NB_MAX];
    int tid = threadIdx.x;
    int c = (tid < NB) ? g_bsum[tid] : 0;
    sm[tid] = c;
    __syncthreads();
    #pragma unroll
    for (int d = 1; d < NB_MAX; d <<= 1) {
        int t = (tid >= d) ? sm[tid - d] : 0;
        __syncthreads();
        sm[tid] += t;
        __syncthreads();
    }
    if (tid < NB) g_bsum[tid] = sm[tid] - c;
}

// Bucket with fused global offset: pos = local_cursor++ + bsum[block(s)].
// Straight-line: 2 loads, 8 independent atomics, 8 bsum adds, 8 stores.
__global__ void bucket_kernel(const int4* __restrict__ idx4, int nquads) {
    int i = (blockIdx.x * blockDim.x + threadIdx.x) * 2;
    if (i >= nquads) return;
    int r = i * 4;
    int4 a = idx4[i];
    int4 b = (i + 1 < nquads) ? idx4[i + 1] : a;

    int p0 = atomicAdd(&g_cur[a.x], 1);
    int p1 = atomicAdd(&g_cur[a.y], 1);
    int p2 = atomicAdd(&g_cur[a.z], 1);
    int p3 = atomicAdd(&g_cur[a.w], 1);
    int p4 = atomicAdd(&g_cur[b.x], 1);
    int p5 = atomicAdd(&g_cur[b.y], 1);
    int p6 = atomicAdd(&g_cur[b.z], 1);
    int p7 = atomicAdd(&g_cur[b.w], 1);

    g_rowid[p0 + g_bsum[a.x >> 10]] = r + 0;
    g_rowid[p1 + g_bsum[a.y >> 10]] = r + 1;
    g_rowid[p2 + g_bsum[a.z >> 10]] = r + 2;
    g_rowid[p3 + g_bsum[a.w >> 10]] = r + 3;
    if (i + 1 < nquads) {
        g_rowid[p4 + g_bsum[b.x >> 10]] = r + 4;
        g_rowid[p5 + g_bsum[b.y >> 10]] = r + 5;
        g_rowid[p6 + g_bsum[b.z >> 10]] = r + 6;
        g_rowid[p7 + g_bsum[b.w >> 10]] = r + 7;
    }
}

// R8 reduce + 4-wide tail step. start = g_loc[gw] + g_bsum[gw>>10].
__global__ void reduce_kernel(const float2* __restrict__ x2,
                              float2* __restrict__ out2,
                              int S) {
    int gw = (blockIdx.x * blockDim.x + threadIdx.x) >> 5;
    int lane = threadIdx.x & 31;
    if (gw >= S) return;

    int start = g_loc[gw] + g_bsum[gw >> 10];
    int cnt   = g_cnt[gw];

    float2 acc0 = {0.f, 0.f}, acc1 = {0.f, 0.f};
    int i = 0;
    for (; i + 8 <= cnt; i += 8) {
        int r0 = g_rowid[start + i + 0];
        int r1 = g_rowid[start + i + 1];
        int r2 = g_rowid[start + i + 2];
        int r3 = g_rowid[start + i + 3];
        int r4 = g_rowid[start + i + 4];
        int r5 = g_rowid[start + i + 5];
        int r6 = g_rowid[start + i + 6];
        int r7 = g_rowid[start + i + 7];
        float2 v0 = __ldcs(x2 + (long long)r0 * 32 + lane);
        float2 v1 = __ldcs(x2 + (long long)r1 * 32 + lane);
        float2 v2 = __ldcs(x2 + (long long)r2 * 32 + lane);
        float2 v3 = __ldcs(x2 + (long long)r3 * 32 + lane);
        float2 v4 = __ldcs(x2 + (long long)r4 * 32 + lane);
        float2 v5 = __ldcs(x2 + (long long)r5 * 32 + lane);
        float2 v6 = __ldcs(x2 + (long long)r6 * 32 + lane);
        float2 v7 = __ldcs(x2 + (long long)r7 * 32 + lane);
        acc0.x += v0.x + v2.x + v4.x + v6.x;
        acc0.y += v0.y + v2.y + v4.y + v6.y;
        acc1.x += v1.x + v3.x + v5.x + v7.x;
        acc1.y += v1.y + v3.y + v5.y + v7.y;
    }
    if (i + 4 <= cnt) {
        int r0 = g_rowid[start + i + 0];
        int r1 = g_rowid[start + i + 1];
        int r2 = g_rowid[start + i + 2];
        int r3 = g_rowid[start + i + 3];
        float2 v0 = __ldcs(x2 + (long long)r0 * 32 + lane);
        float2 v1 = __ldcs(x2 + (long long)r1 * 32 + lane);
        float2 v2 = __ldcs(x2 + (long long)r2 * 32 + lane);
        float2 v3 = __ldcs(x2 + (long long)r3 * 32 + lane);
        acc0.x += v0.x + v2.x;  acc0.y += v0.y + v2.y;
        acc1.x += v1.x + v3.x;  acc1.y += v1.y + v3.y;
        i += 4;
    }
    for (; i < cnt; i++) {
        int r = g_rowid[start + i];
        float2 v = __ldcs(x2 + (long long)r * 32 + lane);
        acc0.x += v.x; acc0.y += v.y;
    }

    float inv = 1.0f / (float)max(cnt, 1);
    float2 o;
    o.x = (acc0.x + acc1.x) * inv;
    o.y = (acc0.y + acc1.y) * inv;
    out2[(long long)gw * 32 + lane] = o;
}

extern "C" void kernel_launch(void* const* d_in, const int* in_sizes, int n_in,
                              void* d_out, int out_size) {
    const float2* x2   = (const float2*)d_in[0];
    const int4*   idx4 = (const int4*)d_in[1];
    float2*       out2 = (float2*)d_out;

    int nrows  = in_sizes[1];        // 4194304
    int S      = out_size / 64;      // 100000
    int nquads = nrows / 4;          // 1048576
    int NB     = (S + SCAN_BLK - 1) / SCAN_BLK;   // 98

    {
        int threads = 256;
        zero_kernel<<<(S + threads - 1) / threads, threads>>>(S);
    }
    {
        int threads = 256;
        int nth = (nquads + 1) / 2;
        hist_kernel<<<(nth + threads - 1) / threads, threads>>>(idx4, nquads);
    }
    scanA_kernel<<<NB, SCAN_BLK>>>(S);
    scanB_kernel<<<1, NB_MAX>>>(NB);
    {
        int threads = 256;
        int nth = (nquads + 1) / 2;
        bucket_kernel<<<(nth + threads - 1) / threads, threads>>>(idx4, nquads);
    }
    {
        int threads = 256;
        int blocks = (S * 32 + threads - 1) / threads;
        reduce_kernel<<<blocks, threads>>>(x2, out2, S);
    }
}